// round 1
// baseline (speedup 1.0000x reference)
#include <cuda_runtime.h>
#include <cstddef>

// DotMatrix: out[b,i,j,t,c] = complex dot over m of A_i and sign-flipped A_j,
// concatenated over ell in {0,1,2,3} (M = 2*ell+1), tau=32 channels each.
//
// Identity used: sum_m A[m]*sign(m)*B[M-1-m]  ==  sum_m (sign(m)*A[M-1-m]) * B[m]
// because sign(M-1-m) == sign(m) (parity symmetric). So the flip+sign is folded
// into the register-resident i-side factor; the j-tile is a raw copy to smem.

namespace cfg {
constexpr int kB = 2;
constexpr int kN = 256;
constexpr int kT = 32;      // taus per ell
constexpr int IT = 16;      // i-tile
constexpr int JT = 16;      // j-tile
constexpr int KI = 2;       // i's per thread (register blocking)
constexpr int TY = IT / KI; // 8
constexpr int NTHREADS = 32 * TY; // 256
// shared tile sizes per ell (floats): JT*kT*(2e+1)*2 = 1024*(2e+1)
// offsets: 1024 * e^2  -> 0, 1024, 4096, 9216 ; total 16384 floats = 64 KiB
constexpr int SH_FLOATS = 16384;
}

__device__ __forceinline__ constexpr int shOff(int ell) { return 1024 * ell * ell; }

template <int ELL>
__device__ __forceinline__ void copyTile(const float* __restrict__ rep,
                                         float* __restrict__ sh,
                                         int b, int j0, int tid) {
  using namespace cfg;
  constexpr int M = 2 * ELL + 1;
  constexpr int CNT4 = (JT * kT * M * 2) / 4;       // 256,768,1280,1792
  constexpr int ITERS = CNT4 / NTHREADS;            // 1,3,5,7 (exact)
  const float4* src = reinterpret_cast<const float4*>(
      rep + (size_t)(b * kN + j0) * (kT * M * 2));
  float4* dst = reinterpret_cast<float4*>(sh + shOff(ELL));
#pragma unroll
  for (int k = 0; k < ITERS; ++k)
    dst[tid + k * NTHREADS] = src[tid + k * NTHREADS];
}

template <int ELL>
__device__ __forceinline__ void loadA(const float* __restrict__ rep,
                                      int b, int i, int tau,
                                      float* __restrict__ Ap) {
  using namespace cfg;
  constexpr int M = 2 * ELL + 1;
  constexpr int AOFF = 2 * ELL * ELL; // 0,2,8,18
  const float2* src = reinterpret_cast<const float2*>(rep) +
                      (size_t)((b * kN + i) * kT + tau) * M;
#pragma unroll
  for (int m = 0; m < M; ++m) {
    float2 v = __ldg(&src[M - 1 - m]);
    float s = ((m + ELL) & 1) ? -1.0f : 1.0f;
    Ap[AOFF + 2 * m]     = s * v.x;
    Ap[AOFF + 2 * m + 1] = s * v.y;
  }
}

template <int ELL>
__device__ __forceinline__ void computeEll(const float* __restrict__ sh,
                                           const float (&Ap)[cfg::KI][32],
                                           int jl, int tau, int b, int i0, int ty,
                                           int j, float2* __restrict__ out) {
  using namespace cfg;
  constexpr int M = 2 * ELL + 1;
  constexpr int AOFF = 2 * ELL * ELL;
  const float2* bsrc = reinterpret_cast<const float2*>(sh + shOff(ELL)) +
                       (jl * kT + tau) * M;
  float accr[KI], acci[KI];
#pragma unroll
  for (int ki = 0; ki < KI; ++ki) { accr[ki] = 0.f; acci[ki] = 0.f; }
#pragma unroll
  for (int m = 0; m < M; ++m) {
    float2 bv = bsrc[m];
#pragma unroll
    for (int ki = 0; ki < KI; ++ki) {
      float ar = Ap[ki][AOFF + 2 * m];
      float ai = Ap[ki][AOFF + 2 * m + 1];
      accr[ki] = fmaf(ar,  bv.x, accr[ki]);
      accr[ki] = fmaf(-ai, bv.y, accr[ki]);
      acci[ki] = fmaf(ar,  bv.y, acci[ki]);
      acci[ki] = fmaf(ai,  bv.x, acci[ki]);
    }
  }
#pragma unroll
  for (int ki = 0; ki < KI; ++ki) {
    int i = i0 + ty + ki * TY;
    size_t oidx = ((size_t)((b * kN + i) * kN + j)) * 128 + ELL * kT + tau;
    out[oidx] = make_float2(accr[ki], acci[ki]);
  }
}

__global__ void __launch_bounds__(cfg::NTHREADS)
dotmat_kernel(const float* __restrict__ r0, const float* __restrict__ r1,
              const float* __restrict__ r2, const float* __restrict__ r3,
              float2* __restrict__ out) {
  using namespace cfg;
  extern __shared__ float sh[];
  const int tau = threadIdx.x;
  const int ty  = threadIdx.y;
  const int tid = ty * 32 + tau;
  const int j0 = blockIdx.x * JT;
  const int i0 = blockIdx.y * IT;
  const int b  = blockIdx.z;

  copyTile<0>(r0, sh, b, j0, tid);
  copyTile<1>(r1, sh, b, j0, tid);
  copyTile<2>(r2, sh, b, j0, tid);
  copyTile<3>(r3, sh, b, j0, tid);

  // A' (flip+sign folded) for KI i-rows, all 4 ells: 32 floats per row.
  float Ap[KI][32];
#pragma unroll
  for (int ki = 0; ki < KI; ++ki) {
    int i = i0 + ty + ki * TY;
    loadA<0>(r0, b, i, tau, Ap[ki]);
    loadA<1>(r1, b, i, tau, Ap[ki]);
    loadA<2>(r2, b, i, tau, Ap[ki]);
    loadA<3>(r3, b, i, tau, Ap[ki]);
  }
  __syncthreads();

#pragma unroll 2
  for (int jl = 0; jl < JT; ++jl) {
    int j = j0 + jl;
    computeEll<0>(sh, Ap, jl, tau, b, i0, ty, j, out);
    computeEll<1>(sh, Ap, jl, tau, b, i0, ty, j, out);
    computeEll<2>(sh, Ap, jl, tau, b, i0, ty, j, out);
    computeEll<3>(sh, Ap, jl, tau, b, i0, ty, j, out);
  }
}

extern "C" void kernel_launch(void* const* d_in, const int* in_sizes, int n_in,
                              void* d_out, int out_size) {
  (void)in_sizes; (void)n_in; (void)out_size;
  // Idempotent; not a stream op, safe under graph capture.
  cudaFuncSetAttribute(dotmat_kernel,
                       cudaFuncAttributeMaxDynamicSharedMemorySize,
                       cfg::SH_FLOATS * (int)sizeof(float));
  dim3 grid(cfg::kN / cfg::JT, cfg::kN / cfg::IT, cfg::kB);
  dim3 block(32, cfg::TY);
  dotmat_kernel<<<grid, block, cfg::SH_FLOATS * sizeof(float)>>>(
      (const float*)d_in[0], (const float*)d_in[1],
      (const float*)d_in[2], (const float*)d_in[3],
      (float2*)d_out);
}